// round 2
// baseline (speedup 1.0000x reference)
#include <cuda_runtime.h>
#include <cuda_bf16.h>
#include <cstdint>

// ============================================================================
// Problem constants
// ============================================================================
#define B_DIM   256
#define T_DIM   2048
#define K_DIM   64
#define H_DIM   128
#define TILE_T  32
#define N_TILES (T_DIM / TILE_T)   // 64

// sigmoid(5*(mem-1)) = 1 / (1 + 2^(C1*mem + C0))
#define SIG_C1  (-7.2134752044448169f)   // -5 * log2(e)
#define SIG_C0  ( 7.2134752044448169f)
#define SIG_DC1 (-6.4921276840003352f)   // 0.9 * C1

// ============================================================================
// SMEM layout (bytes). Rows padded to 72 halves (144 B) for conflict-free LDSM.
// ============================================================================
#define WSTR      72                       // halves per padded row
#define ROWB      144                      // bytes per padded row
#define SMEM_W_HI 0                        // 128 x 72 halves = 18432 B
#define SMEM_W_LO 18432
#define SMEM_X    36864                    // 2 buffers x (hi 4608 + lo 4608)
#define XBUF(s)   (SMEM_X + (s) * 9216)
#define FF_STR    33                       // floats per ff row (pad)
#define SMEM_FF   55296                    // 2 x (128*33*4 = 16896 B)
#define FFBUF(s)  (SMEM_FF + (s) * 16896)
#define SMEM_TOTAL 89088

// ============================================================================
// Helpers
// ============================================================================
__device__ __forceinline__ uint32_t smem_to_u32(const void* p) {
    uint32_t a;
    asm("{ .reg .u64 t; cvta.to.shared.u64 t, %1; cvt.u32.u64 %0, t; }"
        : "=r"(a) : "l"(p));
    return a;
}

__device__ __forceinline__ float ex2f(float x) {
    float y; asm("ex2.approx.f32 %0, %1;" : "=f"(y) : "f"(x)); return y;
}
__device__ __forceinline__ float rcpf(float x) {
    float y; asm("rcp.approx.f32 %0, %1;" : "=f"(y) : "f"(x)); return y;
}

__device__ __forceinline__ void ldm_x4(uint32_t* r, uint32_t addr) {
    asm volatile("ldmatrix.sync.aligned.m8n8.x4.shared.b16 {%0,%1,%2,%3}, [%4];"
        : "=r"(r[0]), "=r"(r[1]), "=r"(r[2]), "=r"(r[3]) : "r"(addr));
}

__device__ __forceinline__ void mma_bf16(float* d, const uint32_t* a, const uint32_t* b) {
    asm volatile(
        "mma.sync.aligned.m16n8k16.row.col.f32.bf16.bf16.f32 "
        "{%0,%1,%2,%3},{%4,%5,%6,%7},{%8,%9},{%0,%1,%2,%3};"
        : "+f"(d[0]), "+f"(d[1]), "+f"(d[2]), "+f"(d[3])
        : "r"(a[0]), "r"(a[1]), "r"(a[2]), "r"(a[3]), "r"(b[0]), "r"(b[1]));
}

__device__ __forceinline__ uint32_t pack_bf16(__nv_bfloat16 a, __nv_bfloat16 b) {
    return ((uint32_t)__bfloat16_as_ushort(b) << 16) | __bfloat16_as_ushort(a);
}

// fp32 -> (hi, lo) bf16 split, packed as 2 x uint2 (4 halves each)
__device__ __forceinline__ void cvt_pack(float4 v, uint2& hi, uint2& lo) {
    __nv_bfloat16 h0 = __float2bfloat16(v.x);
    __nv_bfloat16 h1 = __float2bfloat16(v.y);
    __nv_bfloat16 h2 = __float2bfloat16(v.z);
    __nv_bfloat16 h3 = __float2bfloat16(v.w);
    __nv_bfloat16 l0 = __float2bfloat16(v.x - __bfloat162float(h0));
    __nv_bfloat16 l1 = __float2bfloat16(v.y - __bfloat162float(h1));
    __nv_bfloat16 l2 = __float2bfloat16(v.z - __bfloat162float(h2));
    __nv_bfloat16 l3 = __float2bfloat16(v.w - __bfloat162float(h3));
    hi.x = pack_bf16(h0, h1); hi.y = pack_bf16(h2, h3);
    lo.x = pack_bf16(l0, l1); lo.y = pack_bf16(l2, l3);
}

// ============================================================================
// Fused warp-specialized kernel. 1 CTA / batch element, 256 threads.
//   warps 0-3 (tid<128): consumer — neuron scan, thread = head
//   warps 4-7: producer — convert x to bf16 split + HMMA GEMM -> ff SMEM
// Named barriers: 1,2 = FREE(slot), 3,4 = READY(slot), 5 = producer-internal
// ============================================================================
__global__ void __launch_bounds__(256, 2)
snn_encoder_kernel(const float* __restrict__ x, const float* __restrict__ W,
                   const float* __restrict__ bvec, float* __restrict__ out) {
    extern __shared__ char smem[];
    const uint32_t sb = smem_to_u32(smem);
    const int tid = threadIdx.x;
    const int b   = blockIdx.x;
    const float* xb = x + (size_t)b * T_DIM * K_DIM;

    // ---- Convert W (128x64 fp32) into padded bf16 hi/lo tiles (all threads)
    {
        const float4* w4 = reinterpret_cast<const float4*>(W);
#pragma unroll
        for (int q = 0; q < 8; ++q) {
            int idx = tid + (q << 8);            // 2048 float4 total
            float4 v = __ldg(&w4[idx]);
            int row = idx >> 4, c4 = idx & 15;
            uint32_t off = (uint32_t)row * ROWB + c4 * 8;
            uint2 hi, lo; cvt_pack(v, hi, lo);
            *reinterpret_cast<uint2*>(smem + SMEM_W_HI + off) = hi;
            *reinterpret_cast<uint2*>(smem + SMEM_W_LO + off) = lo;
        }
    }
    __syncthreads();

    if (tid >= 128) {
        // ==================== PRODUCER ====================
        const int pt   = tid - 128;        // 0..127
        const int lane = pt & 31;
        const int pw   = pt >> 5;          // warp 0..3 -> head rows [32pw, 32pw+32)
        const int j    = lane >> 3;

        // per-lane ldmatrix byte offsets
        const uint32_t a_off = (uint32_t)(((j & 1) * 8 + (lane & 7)) * WSTR + ((j >> 1) * 8)) * 2;
        const uint32_t b_off = (uint32_t)(((j >> 1) * 8 + (lane & 7)) * WSTR + ((j & 1) * 8)) * 2;
        const uint32_t aW_hi = sb + SMEM_W_HI + (uint32_t)(pw * 32) * ROWB + a_off;
        const uint32_t aW_lo = sb + SMEM_W_LO + (uint32_t)(pw * 32) * ROWB + a_off;

        // prologue: load + convert tile 0 into x buffer 0
        float4 xr[4];
        {
            const float4* xt4 = reinterpret_cast<const float4*>(xb);
#pragma unroll
            for (int q = 0; q < 4; ++q) xr[q] = __ldg(&xt4[pt + (q << 7)]);
#pragma unroll
            for (int q = 0; q < 4; ++q) {
                int idx = pt + (q << 7);
                int row = idx >> 4, c4 = idx & 15;
                uint32_t off = (uint32_t)row * ROWB + c4 * 8;
                uint2 hi, lo; cvt_pack(xr[q], hi, lo);
                *reinterpret_cast<uint2*>(smem + XBUF(0) + off)        = hi;
                *reinterpret_cast<uint2*>(smem + XBUF(0) + 4608 + off) = lo;
            }
        }
        asm volatile("bar.sync 5, 128;" ::: "memory");

        for (int i = 0; i < N_TILES; ++i) {
            const int s = i & 1;
            const bool havenext = (i + 1 < N_TILES);

            // prefetch next x tile into regs (hide DRAM latency behind GEMM)
            if (havenext) {
                const float4* xt4 = reinterpret_cast<const float4*>(
                    xb + (size_t)(i + 1) * TILE_T * K_DIM);
#pragma unroll
                for (int q = 0; q < 4; ++q) xr[q] = __ldg(&xt4[pt + (q << 7)]);
            }

            // ---- GEMM tile i: D[32h x 32t] per warp, K=64, 3-term bf16 split
            float d[2][4][4];
#pragma unroll
            for (int mt = 0; mt < 2; ++mt)
#pragma unroll
                for (int nt = 0; nt < 4; ++nt)
#pragma unroll
                    for (int c = 0; c < 4; ++c) d[mt][nt][c] = 0.0f;

            const uint32_t bX_hi = sb + XBUF(s) + b_off;
            const uint32_t bX_lo = bX_hi + 4608;
#pragma unroll
            for (int ks = 0; ks < 4; ++ks) {
                uint32_t ahi[2][4], alo[2][4], bhi[2][4], blo[2][4];
#pragma unroll
                for (int mt = 0; mt < 2; ++mt) {
                    ldm_x4(ahi[mt], aW_hi + (uint32_t)mt * 16 * ROWB + ks * 32);
                    ldm_x4(alo[mt], aW_lo + (uint32_t)mt * 16 * ROWB + ks * 32);
                }
#pragma unroll
                for (int np = 0; np < 2; ++np) {   // n0 = 0, 16 (2 n-tiles each)
                    ldm_x4(bhi[np], bX_hi + (uint32_t)np * 16 * ROWB + ks * 32);
                    ldm_x4(blo[np], bX_lo + (uint32_t)np * 16 * ROWB + ks * 32);
                }
#pragma unroll
                for (int mt = 0; mt < 2; ++mt)
#pragma unroll
                    for (int nt = 0; nt < 4; ++nt) {
                        const uint32_t* bh = &bhi[nt >> 1][(nt & 1) * 2];
                        const uint32_t* bl = &blo[nt >> 1][(nt & 1) * 2];
                        mma_bf16(d[mt][nt], ahi[mt], bh);
                        mma_bf16(d[mt][nt], ahi[mt], bl);
                        mma_bf16(d[mt][nt], alo[mt], bh);
                    }
            }

            // wait for ff slot s to be free (consumer 2 tiles behind)
            if (i >= 2) {
                if (s == 0) asm volatile("bar.sync 1, 256;" ::: "memory");
                else        asm volatile("bar.sync 2, 256;" ::: "memory");
            }

            // ---- store ff tile (layout [h][FF_STR], scattered STS.32)
            {
                float* ffp = reinterpret_cast<float*>(smem + FFBUF(s));
                const int r0 = (lane >> 2);
                const int c0 = 2 * (lane & 3);
#pragma unroll
                for (int mt = 0; mt < 2; ++mt) {
                    int row = pw * 32 + mt * 16 + r0;
#pragma unroll
                    for (int nt = 0; nt < 4; ++nt) {
                        int col = nt * 8 + c0;
                        ffp[row * FF_STR + col]           = d[mt][nt][0];
                        ffp[row * FF_STR + col + 1]       = d[mt][nt][1];
                        ffp[(row + 8) * FF_STR + col]     = d[mt][nt][2];
                        ffp[(row + 8) * FF_STR + col + 1] = d[mt][nt][3];
                    }
                }
            }
            if (s == 0) asm volatile("bar.arrive 3, 256;" ::: "memory");
            else        asm volatile("bar.arrive 4, 256;" ::: "memory");

            // ---- convert prefetched tile i+1 into the other x buffer
            if (havenext) {
                const int sn = (i + 1) & 1;
#pragma unroll
                for (int q = 0; q < 4; ++q) {
                    int idx = pt + (q << 7);
                    int row = idx >> 4, c4 = idx & 15;
                    uint32_t off = (uint32_t)row * ROWB + c4 * 8;
                    uint2 hi, lo; cvt_pack(xr[q], hi, lo);
                    *reinterpret_cast<uint2*>(smem + XBUF(sn) + off)        = hi;
                    *reinterpret_cast<uint2*>(smem + XBUF(sn) + 4608 + off) = lo;
                }
                asm volatile("bar.sync 5, 128;" ::: "memory");
            }
        }
    } else {
        // ==================== CONSUMER ====================
        const int h = tid;                       // head index
        const float bias = __ldg(&bvec[h]);
        float mem = 0.0f, spk = 0.0f;
        float* outp = out + (size_t)b * T_DIM * H_DIM + h;

        for (int i = 0; i < N_TILES; ++i) {
            const int s = i & 1;
            if (s == 0) asm volatile("bar.sync 3, 256;" ::: "memory");
            else        asm volatile("bar.sync 4, 256;" ::: "memory");

            const float* fp = reinterpret_cast<const float*>(smem + FFBUF(s)) + h * FF_STR;
            float r[TILE_T];
#pragma unroll
            for (int t = 0; t < TILE_T; ++t) r[t] = fp[t];   // conflict-free LDS

#pragma unroll
            for (int t = 0; t < TILE_T; ++t) {
                float ff = r[t] + bias;
                float w  = fmaf(mem, SIG_DC1, SIG_C0);   // off critical path
                float p  = ff - spk;
                float z  = fmaf(p, SIG_C1, w);           // C1*mem_new + C0
                mem = fmaf(0.9f, mem, p);
                float e = ex2f(z);
                spk = rcpf(1.0f + e);                    // sigmoid(5*(mem-1))
                outp[(size_t)(i * TILE_T + t) * H_DIM] = spk;
            }

            if (i < N_TILES - 2) {
                if (s == 0) asm volatile("bar.arrive 1, 256;" ::: "memory");
                else        asm volatile("bar.arrive 2, 256;" ::: "memory");
            }
        }
    }
}

// ============================================================================
// Launch. Inputs: x [256,2048,64] f32, W [128,64] f32, b [128] f32 -> out f32
// ============================================================================
extern "C" void kernel_launch(void* const* d_in, const int* in_sizes, int n_in,
                              void* d_out, int out_size) {
    const float* x = (const float*)d_in[0];
    const float* W = (const float*)d_in[1];
    const float* b = (const float*)d_in[2];
    float* out = (float*)d_out;

    cudaFuncSetAttribute(snn_encoder_kernel,
                         cudaFuncAttributeMaxDynamicSharedMemorySize, SMEM_TOTAL);
    snn_encoder_kernel<<<B_DIM, 256, SMEM_TOTAL>>>(x, W, b, out);
}